// round 17
// baseline (speedup 1.0000x reference)
#include <cuda_runtime.h>
#include <math.h>

#define NB 32
#define NH 32
#define DMODEL 4096
#define DKH 128
#define SINKC 4
#define WINDOWC 1020
#define MAXC (SINKC + WINDOWC)   /* 1024 */
#define KT 16                    /* gemm k-tile staged in smem */
#define QKV_KSPLIT 16
#define WO_KSPLIT 32
#define NSPLIT 4                 /* attention position partitions */
#define PART (MAXC / NSPLIT)     /* 256 positions per partition */
#define CHUNK 32                 /* attention rows per cp.async stage */
#define NCHMAX (PART / CHUNK)    /* 8 chunks per partition */

// Attention dynamic smem layout (floats):
//   stage[2] @ 0, 8192 each: K/V rows at +0 (32*128), cos at +4096, sin at +6144
//   q_raw 16384, knew 16512, vnew 16640, q_rot 16768,
//   scores 16896 (256), outp 17152 (8*128), red 18176 (8)
#define ATTN_SMEM_FLOATS 18184
#define A_STAGE(st) ((st) * 8192)
#define A_COS 4096
#define A_SIN 6144
#define A_QRAW 16384
#define A_KNEW 16512
#define A_VNEW 16640
#define A_QROT 16768
#define A_SCORES 16896
#define A_OUTP 17152
#define A_RED 18176

// Scratch (device globals: no allocation allowed)
__device__ float  g_cos[MAXC * 64];
__device__ float  g_sin[MAXC * 64];
__device__ float2 g_xs[NB * DMODEL];                  // split activations (hi,lo)
__device__ float  g_part[48 * NB * DMODEL];           // GEMM K-split partials (25 MB)
__device__ float  g_split[NB * NH * NSPLIT * 132];    // per-partition m,S,acc

// ---------------------------------------------------------------------------
__device__ __forceinline__ unsigned tf32_rna(float x) {
    unsigned r;
    asm("cvt.rna.tf32.f32 %0, %1;" : "=r"(r) : "f"(x));
    return r;
}

__device__ __forceinline__ void mma_tf32(float& d0, float& d1, float& d2, float& d3,
                                         unsigned a0, unsigned a1, unsigned a2, unsigned a3,
                                         unsigned b0, unsigned b1) {
    asm("mma.sync.aligned.m16n8k8.row.col.f32.tf32.tf32.f32 "
        "{%0,%1,%2,%3}, {%4,%5,%6,%7}, {%8,%9}, {%0,%1,%2,%3};"
        : "+f"(d0), "+f"(d1), "+f"(d2), "+f"(d3)
        : "r"(a0), "r"(a1), "r"(a2), "r"(a3), "r"(b0), "r"(b1));
}

__device__ __forceinline__ void cp16(void* smem_dst, const void* gsrc) {
    unsigned d = (unsigned)__cvta_generic_to_shared(smem_dst);
    asm volatile("cp.async.cg.shared.global [%0], [%1], 16;" :: "r"(d), "l"(gsrc));
}
#define CP_COMMIT() asm volatile("cp.async.commit_group;")
#define CP_WAIT1()  asm volatile("cp.async.wait_group 1;")
#define CP_WAIT0()  asm volatile("cp.async.wait_group 0;")

// ---------------------------------------------------------------------------
__global__ void noop_kernel() {}     // positions the QKV GEMM at launch 4 for ncu

// ---------------------------------------------------------------------------
// RoPE tables: cos/sin(pos * theta_j), theta_j = 10000^(-j/64), fp32 like ref
// ---------------------------------------------------------------------------
__global__ void rope_table_kernel() {
    int i = blockIdx.x * blockDim.x + threadIdx.x;   // 0 .. MAXC*64-1
    int pos = i >> 6;
    int j = i & 63;
    float theta = powf(10000.0f, -(float)j / 64.0f);
    float ang = (float)pos * theta;
    float s, c;
    sincosf(ang, &s, &c);
    g_cos[i] = c;
    g_sin[i] = s;
}

// ---------------------------------------------------------------------------
// Split activations into (hi, lo) tf32 pair for 3xTF32.
// ---------------------------------------------------------------------------
__global__ void split_kernel(const float* __restrict__ src) {
    int i = blockIdx.x * blockDim.x + threadIdx.x;   // 0 .. NB*DMODEL-1
    float v = src[i];
    unsigned hb = tf32_rna(v);
    float hf = __uint_as_float(hb);
    unsigned lb = tf32_rna(v - hf);
    g_xs[i] = make_float2(hf, __uint_as_float(lb));
}

// ---------------------------------------------------------------------------
// tf32 MMA GEMM, cp.async double-buffered, KT=16 tiles (31 KB smem ->
// 4 blocks/SM). W tile 128x16 stride 20 (A-frag LDS conflict-free: 20r+c
// covers 32 banks); B tile 32x16 hi/lo float2 stride 18 (36r mod 32 = 4r,
// conflict-free per phase). 3xTF32: D += Ah*Bh + Ah*Bl + Al*Bh.
// grid = (32, ksplit, nslots).
// ---------------------------------------------------------------------------
__global__ __launch_bounds__(256, 4)
void mma_gemm_kernel(const float* __restrict__ Wa,
                     const float* __restrict__ Wb,
                     const float* __restrict__ Wc,
                     int ksplit) {
    __shared__ float  sw[2][128 * 20];
    __shared__ float2 sb[2][32 * 18];

    int slot = blockIdx.z;
    const float* W = (slot == 0) ? Wa : (slot == 1) ? Wb : Wc;
    int tid = threadIdx.x;
    int warp = tid >> 5;
    int lane = tid & 31;
    int r = lane >> 2;          // groupID
    int c = lane & 3;           // threadID_in_group
    int rowbase = blockIdx.x * 128;
    int kchunk = DMODEL / ksplit;
    int ntiles = kchunk / KT;
    int kb = blockIdx.y * kchunk;

    // Staging coords: W = 512 float4 (2/thread), B = 256 float4 (1/thread)
    int bbv = tid >> 3;                  // B row (batch)
    int kq  = tid & 7;                   // B float4 index (2 k each)

    float d[4][4];
    #pragma unroll
    for (int t = 0; t < 4; t++)
        d[t][0] = d[t][1] = d[t][2] = d[t][3] = 0.0f;

    auto issue_tile = [&](int kt, int st) {
        #pragma unroll
        for (int i = 0; i < 2; i++) {
            int idx = i * 256 + tid;
            int row = idx >> 2;
            int c4 = (idx & 3) << 2;
            cp16(&sw[st][row * 20 + c4],
                 W + (size_t)(rowbase + row) * DMODEL + kt + c4);
        }
        cp16(&sb[st][bbv * 18 + kq * 2],
             (const float4*)g_xs + (size_t)bbv * (DMODEL / 2) + (kt >> 1) + kq);
        CP_COMMIT();
    };

    issue_tile(kb, 0);

    for (int t = 0; t < ntiles; t++) {
        int st = t & 1;
        if (t + 1 < ntiles) { issue_tile(kb + (t + 1) * KT, st ^ 1); CP_WAIT1(); }
        else                { CP_WAIT0(); }
        __syncthreads();

        const float*  swp = sw[st];
        const float2* sbp = sb[st];
        #pragma unroll
        for (int ko = 0; ko < KT; ko += 8) {
            const float* wrow = swp + (warp * 16 + r) * 20 + ko + c;
            float wa0 = wrow[0];
            float wa1 = wrow[8 * 20];
            float wa2 = wrow[4];
            float wa3 = wrow[8 * 20 + 4];
            unsigned ah0 = __float_as_uint(wa0) & 0xffffe000u;
            unsigned ah1 = __float_as_uint(wa1) & 0xffffe000u;
            unsigned ah2 = __float_as_uint(wa2) & 0xffffe000u;
            unsigned ah3 = __float_as_uint(wa3) & 0xffffe000u;
            unsigned al0 = __float_as_uint(wa0 - __uint_as_float(ah0));
            unsigned al1 = __float_as_uint(wa1 - __uint_as_float(ah1));
            unsigned al2 = __float_as_uint(wa2 - __uint_as_float(ah2));
            unsigned al3 = __float_as_uint(wa3 - __uint_as_float(ah3));

            #pragma unroll
            for (int tb = 0; tb < 4; tb++) {
                float2 xb0 = sbp[(tb * 8 + r) * 18 + ko + c];
                float2 xb1 = sbp[(tb * 8 + r) * 18 + ko + c + 4];
                unsigned bh0 = __float_as_uint(xb0.x), bh1 = __float_as_uint(xb1.x);
                unsigned bl0 = __float_as_uint(xb0.y), bl1 = __float_as_uint(xb1.y);
                mma_tf32(d[tb][0], d[tb][1], d[tb][2], d[tb][3], ah0, ah1, ah2, ah3, bl0, bl1);
                mma_tf32(d[tb][0], d[tb][1], d[tb][2], d[tb][3], al0, al1, al2, al3, bh0, bh1);
                mma_tf32(d[tb][0], d[tb][1], d[tb][2], d[tb][3], ah0, ah1, ah2, ah3, bh0, bh1);
            }
        }
        __syncthreads();
    }

    // c-fragment (m16n8): d0 -> (row n0+r, batch bt+2c); d1 -> batch+1; d2/d3 -> row+8.
    int n0 = rowbase + warp * 16;
    float* pp = g_part + (size_t)(slot * ksplit + blockIdx.y) * NB * DMODEL;
    #pragma unroll
    for (int t = 0; t < 4; t++) {
        int bt = t * 8;
        pp[(size_t)(bt + 2 * c)     * DMODEL + n0 + r]     = d[t][0];
        pp[(size_t)(bt + 2 * c + 1) * DMODEL + n0 + r]     = d[t][1];
        pp[(size_t)(bt + 2 * c)     * DMODEL + n0 + r + 8] = d[t][2];
        pp[(size_t)(bt + 2 * c + 1) * DMODEL + n0 + r + 8] = d[t][3];
    }
}

// ---------------------------------------------------------------------------
// Reduce ksplit partials (W_O only). Layout [ks][b][n], slot 0.
// ---------------------------------------------------------------------------
__global__ void reduce_kernel(float* __restrict__ dst, int ksplit) {
    int i = blockIdx.x * blockDim.x + threadIdx.x;
    int per_slot = NB * (DMODEL / 4);
    if (i >= per_slot) return;
    const float4* src = (const float4*)g_part + i;
    float4 s = make_float4(0.f, 0.f, 0.f, 0.f);
    for (int k = 0; k < ksplit; k++) {
        float4 v = src[(size_t)k * per_slot];
        s.x += v.x; s.y += v.y; s.z += v.z; s.w += v.w;
    }
    ((float4*)dst)[i] = s;
}

// ---------------------------------------------------------------------------
// Attention: flash-decode split + cp.async staging of K/V AND cos/sin tables.
// (Unchanged from R16 except QKV_KSPLIT=16 in the prologue.)
// ---------------------------------------------------------------------------
__device__ __forceinline__ int cache_row(int p, bool full, int ins, int part2) {
    if (!full || p < SINKC) return p;
    return (p < SINKC + part2) ? (ins + 1 + (p - SINKC))
                               : (SINKC + (p - SINKC - part2));
}

__global__ void attn_kernel(const float* __restrict__ kcache,
                            const float* __restrict__ vcache,
                            const int* __restrict__ seqp) {
    extern __shared__ float sm[];
    float* scores = sm + A_SCORES;
    float* red    = sm + A_RED;

    int bh = blockIdx.x;
    int sp = blockIdx.y;
    int b = bh >> 5;
    int h = bh & 31;
    int tid = threadIdx.x, warp = tid >> 5, lane = tid & 31;
    int l16 = lane & 15, hw = lane >> 4;

    int seq = *seqp;
    int L, ins, part2;
    bool full;
    if (seq < MAXC) { L = seq + 1; ins = seq; part2 = 0; full = false; }
    else { L = MAXC; ins = SINKC + (seq - SINKC) % WINDOWC; part2 = MAXC - (ins + 1); full = true; }

    int ps = sp * PART;
    int pe = min(ps + PART, L);
    int nch = 0;
    if (pe > ps) nch = min(NCHMAX, (pe - ps + CHUNK - 1) / CHUNK);
    bool need_new = (L - 1 >= ps) && (L - 1 < ps + PART);

    const float* kbf = kcache + (size_t)bh * MAXC * DKH;
    const float* vbf = vcache + (size_t)bh * MAXC * DKH;

    int srow = tid >> 3;
    int scol = (tid & 7) << 2;

    auto issue_k = [&](int ch, int st) {
        int p = ps + ch * CHUNK + srow;
        int cr = (p < L) ? cache_row(p, full, ins, part2) : 0;
        const float* src = kbf + (size_t)cr * DKH + scol;
        float* dst = sm + A_STAGE(st) + srow * DKH + scol;
        #pragma unroll
        for (int j = 0; j < 4; j++) cp16(dst + j * 32, src + j * 32);
        int tb = (ps + ch * CHUNK) * 64;
        float* cdst = sm + A_STAGE(st) + A_COS + tid * 8;
        const float* csrc = g_cos + tb + tid * 8;
        cp16(cdst, csrc); cp16(cdst + 4, csrc + 4);
        float* sdst = sm + A_STAGE(st) + A_SIN + tid * 8;
        const float* ssrc = g_sin + tb + tid * 8;
        cp16(sdst, ssrc); cp16(sdst + 4, ssrc + 4);
        CP_COMMIT();
    };
    auto issue_v = [&](int ch, int st) {
        int p = ps + ch * CHUNK + srow;
        int cr = (p < L) ? cache_row(p, full, ins, part2) : 0;
        const float* src = vbf + (size_t)cr * DKH + scol;
        float* dst = sm + A_STAGE(st) + srow * DKH + scol;
        #pragma unroll
        for (int j = 0; j < 4; j++) cp16(dst + j * 32, src + j * 32);
        CP_COMMIT();
    };
    auto fix_row = [&](int ch, int st, const float* newv) {
        int fr = (L - 1) - (ps + ch * CHUNK);
        if (fr >= 0 && fr < CHUNK) {
            if (tid < DKH) sm[A_STAGE(st) + fr * DKH + tid] = newv[tid];
            __syncthreads();
        }
    };

    // ---- prologue: reduce QKV K-split partials for this (b,h) ----
    for (int i = tid; i < 3 * DKH; i += 256) {
        int slot = i >> 7;           // 0=q, 1=k_new, 2=v_new
        if (slot != 0 && !need_new) continue;
        int d = i & (DKH - 1);
        const float* base = g_part
            + ((size_t)(slot * QKV_KSPLIT) * NB + b) * DMODEL + h * DKH + d;
        float s = 0.0f;
        #pragma unroll
        for (int ks = 0; ks < QKV_KSPLIT; ks++)
            s += base[(size_t)ks * NB * DMODEL];
        float* dsts = (slot == 0) ? (sm + A_QRAW) : (slot == 1) ? (sm + A_KNEW) : (sm + A_VNEW);
        dsts[d] = s;
    }
    if (nch > 0) issue_k(0, 0);
    __syncthreads();

    if (tid < DKH) {
        float qv = sm[A_QRAW + tid];
        float pn = sm[A_QRAW + (tid ^ 64)];
        int j = tid & 63;
        float c = g_cos[(L - 1) * 64 + j];
        float s = g_sin[(L - 1) * 64 + j];
        float flip = (tid < 64) ? -pn : pn;
        sm[A_QROT + tid] = qv * c + flip * s;
    }
    __syncthreads();

    float4 ql = *(const float4*)(sm + A_QROT + l16 * 4);
    float4 qh = *(const float4*)(sm + A_QROT + 64 + l16 * 4);

    // ---- phase 1: scores (all-LDS inner loop) ----
    for (int ch = 0; ch < nch; ch++) {
        int st = ch & 1;
        if (ch + 1 < nch) { issue_k(ch + 1, st ^ 1); CP_WAIT1(); }
        else              { CP_WAIT0(); }
        __syncthreads();
        fix_row(ch, st, sm + A_KNEW);

        const float* stp = sm + A_STAGE(st);
        int pb = ps + ch * CHUNK;
        #pragma unroll
        for (int i = 0; i < 2; i++) {
            int row = warp * 4 + i * 2 + hw;   // half-warp owns one row
            int p = pb + row;
            const float* kr = stp + row * DKH;
            float4 klo = *(const float4*)(kr + l16 * 4);
            float4 khi = *(const float4*)(kr + 64 + l16 * 4);
            float4 c4 = *(const float4*)(stp + A_COS + row * 64 + l16 * 4);
            float4 s4 = *(const float4*)(stp + A_SIN + row * 64 + l16 * 4);

            float d = klo.x * (c4.x * ql.x + s4.x * qh.x)
                    + khi.x * (c4.x * qh.x - s4.x * ql.x)
                    + klo.y * (c4.y * ql.y + s4.y * qh.y)
                    + khi.y * (c4.y * qh.y - s4.y * ql.y)
                    + klo.z * (c4.z * ql.z + s4.z * qh.z)
                    + khi.z * (c4.z * qh.z - s4.z * ql.z)
                    + klo.w * (c4.w * ql.w + s4.w * qh.w)
                    + khi.w * (c4.w * qh.w - s4.w * ql.w);
            #pragma unroll
            for (int o = 8; o > 0; o >>= 1)
                d += __shfl_xor_sync(0xffffffffu, d, o);
            if (l16 == 0 && p < pe)
                scores[p - ps] = d * 0.08838834764831845f;   // 1/sqrt(128)
        }
        __syncthreads();
    }

    if (nch > 0) issue_v(0, 0);

    // ---- partition softmax stats ----
    int n = pe - ps;
    float m = -1e30f;
    for (int p = tid; p < n; p += 256) m = fmaxf(m, scores[p]);
    #pragma unroll
    for (int o = 16; o > 0; o >>= 1) m = fmaxf(m, __shfl_xor_sync(0xffffffffu, m, o));
    if (lane == 0) red[warp] = m;
    __syncthreads();
    m = red[0];
    #pragma unroll
    for (int w = 1; w < 8; w++) m = fmaxf(m, red[w]);

    float lsum = 0.0f;
    for (int p = tid; p < n; p += 256) {
        float e = __expf(scores[p] - m);
        scores[p] = e;
        lsum += e;
    }
    #pragma unroll
    for (int o = 16; o > 0; o >>= 1) lsum += __shfl_xor_sync(0xffffffffu, lsum, o);
    __syncthreads();
    if (lane == 0) red[warp] = lsum;
    __syncthreads();
    float S = 0.0f;
    #pragma unroll
    for (int w = 0; w < 8; w++) S += red[w];

    // ---- phase 2: unnormalized acc over V chunks ----
    float4 acc = make_float4(0.f, 0.f, 0.f, 0.f);
    for (int ch = 0; ch < nch; ch++) {
        int st = ch & 1;
        if (ch + 1 < nch) { issue_v(ch + 1, st ^ 1); CP_WAIT1(); }
        else              { CP_WAIT0(); }
        __syncthreads();
        fix_row(ch, st, sm + A_VNEW);

        const float* stp = sm + A_STAGE(st);
        int pb = ps + ch * CHUNK;
        #pragma unroll
        for (int i = 0; i < 4; i++) {
            int row = warp * 4 + i;
            int p = pb + row;
            float w8 = (p < pe) ? scores[p - ps] : 0.0f;
            float4 vv = *(const float4*)(stp + row * DKH + lane * 4);
            acc.x += w8 * vv.x;
            acc.y += w8 * vv.y;
            acc.z += w8 * vv.z;
            acc.w += w8 * vv.w;
        }
        __syncthreads();
    }

    *(float4*)(sm + A_OUTP + warp * DKH + lane * 4) = acc;
    __syncthreads();

    float* dst = g_split + ((size_t)bh * NSPLIT + sp) * 132;
    if (tid < DKH) {
        float s = 0.0f;
        #pragma unroll
        for (int w = 0; w < 8; w++) s += sm[A_OUTP + w * DKH + tid];
        dst[tid] = s;
    } else if (tid == 128) {
        dst[128] = m;
        dst[129] = S;
    }
}

// ---------------------------------------------------------------------------
// Combine partitions: out = (sum_s w_s acc_s) / (sum_s w_s S_s), w_s=e^{m_s-m}.
// Writes the tf32 hi/lo split activations for the W_O GEMM.
// ---------------------------------------------------------------------------
__global__ void combine_kernel() {
    __shared__ float w[NSPLIT];
    __shared__ float Ssh;
    int bh = blockIdx.x;
    int tid = threadIdx.x;
    int b = bh >> 5;
    int h = bh & 31;
    const float* base = g_split + (size_t)bh * NSPLIT * 132;

    if (tid == 0) {
        float ms[NSPLIT], Ss[NSPLIT];
        float m = -1e30f;
        #pragma unroll
        for (int s = 0; s < NSPLIT; s++) {
            ms[s] = base[s * 132 + 128];
            Ss[s] = base[s * 132 + 129];
            m = fmaxf(m, ms[s]);
        }
        float S = 0.0f;
        #pragma unroll
        for (int s = 0; s < NSPLIT; s++) {
            float ws = __expf(ms[s] - m);
            w[s] = ws;
            S += ws * Ss[s];
        }
        Ssh = S;
    }
    __syncthreads();

    float a = 0.0f;
    #pragma unroll
    for (int s = 0; s < NSPLIT; s++) a += w[s] * base[s * 132 + tid];
    float v = a / Ssh;
    unsigned hb = tf32_rna(v);
    float hf = __uint_as_float(hb);
    unsigned lb = tf32_rna(v - hf);
    g_xs[(size_t)b * DMODEL + h * DKH + tid] = make_float2(hf, __uint_as_float(lb));
}

// ---------------------------------------------------------------------------
extern "C" void kernel_launch(void* const* d_in, const int* in_sizes, int n_in,
                              void* d_out, int out_size) {
    const float* x  = (const float*)d_in[0];
    const float* kc = (const float*)d_in[1];
    const float* vc = (const float*)d_in[2];
    const float* Wq = (const float*)d_in[3];
    const float* Wk = (const float*)d_in[4];
    const float* Wv = (const float*)d_in[5];
    const float* Wo = (const float*)d_in[6];
    const int* seqp = (const int*)d_in[7];
    float* out = (float*)d_out;

    const int attn_smem = ATTN_SMEM_FLOATS * sizeof(float);   // ~71 KB
    cudaFuncSetAttribute(attn_kernel,
                         cudaFuncAttributeMaxDynamicSharedMemorySize, attn_smem);

    split_kernel<<<512, 256>>>(x);                                          // 1
    rope_table_kernel<<<64, 1024>>>();                                      // 2
    noop_kernel<<<1, 1>>>();                                                // 3
    mma_gemm_kernel<<<dim3(32, QKV_KSPLIT, 3), 256>>>(Wq, Wk, Wv, QKV_KSPLIT); // 4 (profiled)
    attn_kernel<<<dim3(NB * NH, NSPLIT), 256, attn_smem>>>(kc, vc, seqp);   // 5
    combine_kernel<<<NB * NH, 128>>>();                                     // 6
    mma_gemm_kernel<<<dim3(32, WO_KSPLIT, 1), 256>>>(Wo, Wo, Wo, WO_KSPLIT); // 7
    reduce_kernel<<<128, 256>>>(out, WO_KSPLIT);                            // 8
}